// round 1
// baseline (speedup 1.0000x reference)
#include <cuda_runtime.h>
#include <math.h>

#define NB   4096          // batch (anchors)
#define ND   512           // embedding dim
#define NPOS 8192          // positives (P = 2)
#define INV_T 14.2857142857142857f   // 1/0.07
#define NCOLT 32           // column tiles in GEMM (4096/128)

// ---- scratch (no allocation allowed) ----
__device__ float g_anorm[NB * ND];        // normalized anchors, 8 MB
__device__ float g_partial[NB * NCOLT];   // per-(row, coltile) exp-sums
__device__ float g_neg[NB];               // neg_sumexp per row
__device__ float g_losspart[1024];        // per-block loss partials

// ---------------------------------------------------------------------------
// 1) L2-normalize anchors. One warp per row (512 floats = 4 float4 per lane).
// ---------------------------------------------------------------------------
__global__ void normalize_kernel(const float* __restrict__ a) {
    int warp = threadIdx.x >> 5;
    int lane = threadIdx.x & 31;
    int row  = blockIdx.x * 8 + warp;

    const float4* src = (const float4*)(a + (size_t)row * ND);
    float4*       dst = (float4*)(g_anorm + (size_t)row * ND);

    float4 v[4];
    float ss = 0.f;
#pragma unroll
    for (int q = 0; q < 4; q++) {
        v[q] = src[lane + 32 * q];
        ss += v[q].x * v[q].x + v[q].y * v[q].y + v[q].z * v[q].z + v[q].w * v[q].w;
    }
#pragma unroll
    for (int o = 16; o > 0; o >>= 1) ss += __shfl_xor_sync(0xffffffffu, ss, o);

    float inv = rsqrtf(ss);
#pragma unroll
    for (int q = 0; q < 4; q++) {
        float4 w = v[q];
        w.x *= inv; w.y *= inv; w.z *= inv; w.w *= inv;
        dst[lane + 32 * q] = w;
    }
}

// ---------------------------------------------------------------------------
// 2) aa = a_norm @ a_norm^T ; epilogue: exp(aa/T) with diagonal skipped,
//    per-row partial sums written to g_partial[row][coltile].
//    128x128 tile, BK=16, 256 threads, 8x8 per thread (4+4 split columns/rows).
// ---------------------------------------------------------------------------
__global__ __launch_bounds__(256) void aa_kernel() {
    __shared__ float As[16][132];   // [k][m], 132 pad (mult of 4 -> float4 ok)
    __shared__ float Bs[16][132];   // [k][n]
    __shared__ float rs[128][17];   // row-sum reduction scratch

    const int tid = threadIdx.x;
    const int tx  = tid & 15;       // 0..15 -> columns
    const int ty  = tid >> 4;       // 0..15 -> rows
    const int row0 = blockIdx.y * 128;
    const int col0 = blockIdx.x * 128;

    float acc[8][8];
#pragma unroll
    for (int i = 0; i < 8; i++)
#pragma unroll
        for (int j = 0; j < 8; j++) acc[i][j] = 0.f;

    for (int k0 = 0; k0 < ND; k0 += 16) {
#pragma unroll
        for (int l = 0; l < 2; l++) {
            int idx = tid + l * 256;       // 0..511
            int m   = idx >> 2;            // 0..127
            int k4  = (idx & 3) * 4;       // 0,4,8,12
            float4 va = *(const float4*)(g_anorm + (size_t)(row0 + m) * ND + k0 + k4);
            As[k4 + 0][m] = va.x; As[k4 + 1][m] = va.y;
            As[k4 + 2][m] = va.z; As[k4 + 3][m] = va.w;
            float4 vb = *(const float4*)(g_anorm + (size_t)(col0 + m) * ND + k0 + k4);
            Bs[k4 + 0][m] = vb.x; Bs[k4 + 1][m] = vb.y;
            Bs[k4 + 2][m] = vb.z; Bs[k4 + 3][m] = vb.w;
        }
        __syncthreads();

#pragma unroll
        for (int k = 0; k < 16; k++) {
            float4 a0 = *(const float4*)&As[k][ty * 4];
            float4 a1 = *(const float4*)&As[k][64 + ty * 4];
            float4 b0 = *(const float4*)&Bs[k][tx * 4];
            float4 b1 = *(const float4*)&Bs[k][64 + tx * 4];
            float rm[8] = {a0.x, a0.y, a0.z, a0.w, a1.x, a1.y, a1.z, a1.w};
            float rn[8] = {b0.x, b0.y, b0.z, b0.w, b1.x, b1.y, b1.z, b1.w};
#pragma unroll
            for (int i = 0; i < 8; i++)
#pragma unroll
                for (int j = 0; j < 8; j++) acc[i][j] += rm[i] * rn[j];
        }
        __syncthreads();
    }

    // epilogue: exp(aa * INV_T), skip diagonal, per-row partial sums
    float rp[8];
#pragma unroll
    for (int i = 0; i < 8; i++) rp[i] = 0.f;

#pragma unroll
    for (int i = 0; i < 8; i++) {
        int lr = (i < 4) ? (ty * 4 + i) : (64 + ty * 4 + i - 4);
        int r  = row0 + lr;
#pragma unroll
        for (int j = 0; j < 8; j++) {
            int lc = (j < 4) ? (tx * 4 + j) : (64 + tx * 4 + j - 4);
            int c  = col0 + lc;
            float e = (r == c) ? 0.f : expf(acc[i][j] * INV_T);
            rp[i] += e;
        }
    }
#pragma unroll
    for (int i = 0; i < 8; i++) {
        int lr = (i < 4) ? (ty * 4 + i) : (64 + ty * 4 + i - 4);
        rs[lr][tx] = rp[i];
    }
    __syncthreads();

    if (tid < 128) {
        float s = 0.f;
#pragma unroll
        for (int x = 0; x < 16; x++) s += rs[tid][x];
        g_partial[(size_t)(row0 + tid) * NCOLT + blockIdx.x] = s;
    }
}

// ---------------------------------------------------------------------------
// 3) reduce 32 column-tile partials per row -> neg_sumexp
// ---------------------------------------------------------------------------
__global__ void neg_reduce_kernel() {
    int r = blockIdx.x * 256 + threadIdx.x;
    float s = 0.f;
#pragma unroll
    for (int j = 0; j < NCOLT; j++) s += g_partial[(size_t)r * NCOLT + j];
    g_neg[r] = s;
}

// ---------------------------------------------------------------------------
// 4) pos similarities + per-pair loss; one warp per (b,p) pair.
//    pos_sim = dot(a_norm[b], pos_raw[pair]) * rsqrt(dot(pos,pos)) / T
//    loss    = log(exp(pos_sim) + neg[b] + 1e-8) - pos_sim
// ---------------------------------------------------------------------------
__global__ void loss_kernel(const float* __restrict__ pos) {
    __shared__ float sh[8];
    int warp = threadIdx.x >> 5;
    int lane = threadIdx.x & 31;
    int pair = blockIdx.x * 8 + warp;   // 0..8191
    int b    = pair >> 1;               // P = 2

    const float4* pv = (const float4*)(pos + (size_t)pair * ND);
    const float4* av = (const float4*)(g_anorm + (size_t)b * ND);

    float dap = 0.f, dpp = 0.f;
#pragma unroll
    for (int q = 0; q < 4; q++) {
        float4 p4 = pv[lane + 32 * q];
        float4 a4 = av[lane + 32 * q];
        dap += a4.x * p4.x + a4.y * p4.y + a4.z * p4.z + a4.w * p4.w;
        dpp += p4.x * p4.x + p4.y * p4.y + p4.z * p4.z + p4.w * p4.w;
    }
#pragma unroll
    for (int o = 16; o > 0; o >>= 1) {
        dap += __shfl_xor_sync(0xffffffffu, dap, o);
        dpp += __shfl_xor_sync(0xffffffffu, dpp, o);
    }

    if (lane == 0) {
        float ps = dap * rsqrtf(dpp) * INV_T;
        float ep = expf(ps);
        sh[warp] = logf(ep + g_neg[b] + 1e-8f) - ps;
    }
    __syncthreads();
    if (threadIdx.x == 0) {
        float s = 0.f;
#pragma unroll
        for (int w = 0; w < 8; w++) s += sh[w];
        g_losspart[blockIdx.x] = s;
    }
}

// ---------------------------------------------------------------------------
// 5) final mean
// ---------------------------------------------------------------------------
__global__ void final_kernel(float* __restrict__ out) {
    __shared__ float sh[256];
    float s = 0.f;
    for (int i = threadIdx.x; i < 1024; i += 256) s += g_losspart[i];
    sh[threadIdx.x] = s;
    __syncthreads();
    for (int o = 128; o > 0; o >>= 1) {
        if (threadIdx.x < o) sh[threadIdx.x] += sh[threadIdx.x + o];
        __syncthreads();
    }
    if (threadIdx.x == 0) out[0] = sh[0] * (1.0f / (float)NPOS);
}

// ---------------------------------------------------------------------------
extern "C" void kernel_launch(void* const* d_in, const int* in_sizes, int n_in,
                              void* d_out, int out_size) {
    const float* anchor = (const float*)d_in[0];
    const float* pos    = (const float*)d_in[1];
    // robustness: anchor is the smaller tensor (2M vs 4M elements)
    if (n_in >= 2 && in_sizes[0] > in_sizes[1]) {
        const float* t = anchor; anchor = pos; pos = t;
    }

    normalize_kernel<<<NB / 8, 256>>>(anchor);
    aa_kernel<<<dim3(NCOLT, NCOLT), 256>>>();
    neg_reduce_kernel<<<NB / 256, 256>>>();
    loss_kernel<<<NPOS / 8, 256>>>(pos);
    final_kernel<<<1, 256>>>((float*)d_out);
}

// round 3
// speedup vs baseline: 5.4024x; 5.4024x over previous
#include <cuda_runtime.h>
#include <cuda_bf16.h>
#include <math.h>
#include <cstdint>

#define NB   4096
#define ND   512
#define NPOS 8192
#define INV_T 14.2857142857142857f
#define EXP2_SCALE 20.609929155566063f   /* INV_T * log2(e) */
#define NCOLT 32

// ---- scratch (no allocation allowed) ----
__device__ float         g_anorm[NB * ND];       // normalized anchors fp32
__device__ __nv_bfloat16 g_abf16[NB * ND];       // normalized anchors bf16
__device__ float         g_partial[NB * NCOLT];
__device__ float         g_neg[NB];
__device__ float         g_losspart[1024];

__device__ __forceinline__ uint32_t smem_u32(const void* p) {
    uint32_t a;
    asm("{ .reg .u64 t; cvta.to.shared.u64 t, %1; cvt.u32.u64 %0, t; }" : "=r"(a) : "l"(p));
    return a;
}

// ---------------------------------------------------------------------------
// 1) L2-normalize anchors -> fp32 + bf16 copies. One warp per row.
// ---------------------------------------------------------------------------
__global__ void normalize_kernel(const float* __restrict__ a) {
    int warp = threadIdx.x >> 5;
    int lane = threadIdx.x & 31;
    int row  = blockIdx.x * 8 + warp;

    const float4* src = (const float4*)(a + (size_t)row * ND);
    float4*       dst = (float4*)(g_anorm + (size_t)row * ND);
    __nv_bfloat162* bdst = (__nv_bfloat162*)(g_abf16 + (size_t)row * ND);

    float4 v[4];
    float ss = 0.f;
#pragma unroll
    for (int q = 0; q < 4; q++) {
        v[q] = src[lane + 32 * q];
        ss += v[q].x * v[q].x + v[q].y * v[q].y + v[q].z * v[q].z + v[q].w * v[q].w;
    }
#pragma unroll
    for (int o = 16; o > 0; o >>= 1) ss += __shfl_xor_sync(0xffffffffu, ss, o);

    float inv = rsqrtf(ss);
#pragma unroll
    for (int q = 0; q < 4; q++) {
        float4 w = v[q];
        w.x *= inv; w.y *= inv; w.z *= inv; w.w *= inv;
        dst[lane + 32 * q] = w;
        int i = lane + 32 * q;
        bdst[2 * i]     = __floats2bfloat162_rn(w.x, w.y);
        bdst[2 * i + 1] = __floats2bfloat162_rn(w.z, w.w);
    }
}

// ---------------------------------------------------------------------------
// 2) mma.sync bf16 GEMM: aa = Â·Âᵀ, 128x128 CTA tile, 8 warps (2x4),
//    64x32 warp tile, K chunk 32, cp.async double buffer, fused exp epilogue.
//    SMEM tile layout: 128 rows x 64B (4 x 16B slots), slot ^= (row>>1)&3.
// ---------------------------------------------------------------------------
#define KC 32
#define NCHUNK (ND / KC)      // 16
#define TILE_BYTES (128 * 64) // 8KB

__global__ __launch_bounds__(256) void aa_mma_kernel() {
    __shared__ __align__(128) char sA[2][TILE_BYTES];
    __shared__ __align__(128) char sB[2][TILE_BYTES];
    __shared__ float rs[128][4];

    const int tid = threadIdx.x;
    const int wid = tid >> 5;
    const int l   = tid & 31;
    const int wr  = wid & 1;       // 0..1  -> m offset 64*wr
    const int wc  = wid >> 1;      // 0..3  -> n offset 32*wc
    const int row0 = blockIdx.y * 128;
    const int col0 = blockIdx.x * 128;

    const uint32_t sa_base = smem_u32(sA);
    const uint32_t sb_base = smem_u32(sB);
    const char* gsrc = (const char*)g_abf16;

    // per-lane ldmatrix byte offsets within a tile (per k-half kc)
    // A (m16xk16 via x4): lanes 0-7 rows 0-7 klo, 8-15 rows 8-15 klo,
    //                     16-23 rows 0-7 khi, 24-31 rows 8-15 khi
    const int ra = (l & 7) | (((l >> 3) & 1) << 3);
    const int sa_hi = l >> 4;
    // B (n16xk16 via x4): lanes 0-7 n0-7 klo, 8-15 n0-7 khi,
    //                     16-23 n8-15 klo, 24-31 n8-15 khi
    const int rb = (l & 7) | ((l >> 4) << 3);
    const int sb_hi = (l >> 3) & 1;

    uint32_t offA[2], offB[2];
#pragma unroll
    for (int kc = 0; kc < 2; kc++) {
        offA[kc] = ra * 64 + (((2 * kc + sa_hi) ^ ((ra >> 1) & 3)) << 4);
        offB[kc] = rb * 64 + (((2 * kc + sb_hi) ^ ((rb >> 1) & 3)) << 4);
    }

    // cp.async indices: thread covers 2 x 16B per tile
    int ld_row[2], ld_slot[2];
    uint32_t ld_dst[2];
#pragma unroll
    for (int t = 0; t < 2; t++) {
        int idx = tid + t * 256;       // 0..511
        ld_row[t]  = idx >> 2;
        ld_slot[t] = idx & 3;
        int sw = ld_slot[t] ^ ((ld_row[t] >> 1) & 3);
        ld_dst[t] = ld_row[t] * 64 + sw * 16;
    }

    float acc[4][4][4];
#pragma unroll
    for (int i = 0; i < 4; i++)
#pragma unroll
        for (int j = 0; j < 4; j++)
#pragma unroll
            for (int q = 0; q < 4; q++) acc[i][j][q] = 0.f;

    // ---- prologue: load chunk 0 into buf 0 ----
#pragma unroll
    for (int t = 0; t < 2; t++) {
        const char* srcA = gsrc + ((size_t)(row0 + ld_row[t]) * ND + ld_slot[t] * 8) * 2;
        const char* srcB = gsrc + ((size_t)(col0 + ld_row[t]) * ND + ld_slot[t] * 8) * 2;
        asm volatile("cp.async.cg.shared.global [%0], [%1], 16;" :: "r"(sa_base + ld_dst[t]), "l"(srcA) : "memory");
        asm volatile("cp.async.cg.shared.global [%0], [%1], 16;" :: "r"(sb_base + ld_dst[t]), "l"(srcB) : "memory");
    }
    asm volatile("cp.async.commit_group;" ::: "memory");

    for (int c = 0; c < NCHUNK; c++) {
        int buf = c & 1;
        if (c + 1 < NCHUNK) {
            int nb = (c + 1) & 1;
            int kbyte = (c + 1) * KC * 2;
#pragma unroll
            for (int t = 0; t < 2; t++) {
                const char* srcA = gsrc + ((size_t)(row0 + ld_row[t]) * ND) * 2 + kbyte + ld_slot[t] * 16;
                const char* srcB = gsrc + ((size_t)(col0 + ld_row[t]) * ND) * 2 + kbyte + ld_slot[t] * 16;
                asm volatile("cp.async.cg.shared.global [%0], [%1], 16;" :: "r"(sa_base + nb * TILE_BYTES + ld_dst[t]), "l"(srcA) : "memory");
                asm volatile("cp.async.cg.shared.global [%0], [%1], 16;" :: "r"(sb_base + nb * TILE_BYTES + ld_dst[t]), "l"(srcB) : "memory");
            }
            asm volatile("cp.async.commit_group;" ::: "memory");
            asm volatile("cp.async.wait_group 1;" ::: "memory");
        } else {
            asm volatile("cp.async.wait_group 0;" ::: "memory");
        }
        __syncthreads();

        const uint32_t aw = sa_base + buf * TILE_BYTES + wr * 64 * 64;   // warp A base
        const uint32_t bw = sb_base + buf * TILE_BYTES + wc * 32 * 64;   // warp B base

#pragma unroll
        for (int kc = 0; kc < 2; kc++) {
            uint32_t af[4][4];     // [mf][4 regs]
#pragma unroll
            for (int mf = 0; mf < 4; mf++) {
                asm volatile("ldmatrix.sync.aligned.m8n8.x4.shared.b16 {%0,%1,%2,%3}, [%4];"
                    : "=r"(af[mf][0]), "=r"(af[mf][1]), "=r"(af[mf][2]), "=r"(af[mf][3])
                    : "r"(aw + mf * 16 * 64 + offA[kc]));
            }
            uint32_t bf[4][2];     // [nf][2 regs]
#pragma unroll
            for (int p = 0; p < 2; p++) {
                uint32_t r0, r1, r2, r3;
                asm volatile("ldmatrix.sync.aligned.m8n8.x4.shared.b16 {%0,%1,%2,%3}, [%4];"
                    : "=r"(r0), "=r"(r1), "=r"(r2), "=r"(r3)
                    : "r"(bw + p * 16 * 64 + offB[kc]));
                bf[2 * p][0] = r0; bf[2 * p][1] = r1;
                bf[2 * p + 1][0] = r2; bf[2 * p + 1][1] = r3;
            }
#pragma unroll
            for (int mf = 0; mf < 4; mf++)
#pragma unroll
                for (int nf = 0; nf < 4; nf++) {
                    asm volatile(
                        "mma.sync.aligned.m16n8k16.row.col.f32.bf16.bf16.f32 "
                        "{%0,%1,%2,%3}, {%4,%5,%6,%7}, {%8,%9}, {%0,%1,%2,%3};"
                        : "+f"(acc[mf][nf][0]), "+f"(acc[mf][nf][1]),
                          "+f"(acc[mf][nf][2]), "+f"(acc[mf][nf][3])
                        : "r"(af[mf][0]), "r"(af[mf][1]), "r"(af[mf][2]), "r"(af[mf][3]),
                          "r"(bf[nf][0]), "r"(bf[nf][1]));
                }
        }
        __syncthreads();
    }

    // ---- fused epilogue: exp, diag skip, row sums ----
    const bool diag = (blockIdx.x == blockIdx.y);
    const int qrow = l >> 2;           // 0..7
    const int qcol = 2 * (l & 3);      // 0,2,4,6

#pragma unroll
    for (int mf = 0; mf < 4; mf++) {
        float slo = 0.f, shi = 0.f;
        int rlo = wr * 64 + mf * 16 + qrow;        // local row (lo)
#pragma unroll
        for (int nf = 0; nf < 4; nf++) {
            int cb = wc * 32 + nf * 8 + qcol;      // local col base
            float e0 = exp2f(acc[mf][nf][0] * EXP2_SCALE);
            float e1 = exp2f(acc[mf][nf][1] * EXP2_SCALE);
            float e2 = exp2f(acc[mf][nf][2] * EXP2_SCALE);
            float e3 = exp2f(acc[mf][nf][3] * EXP2_SCALE);
            if (diag) {
                if (rlo == cb)         e0 = 0.f;
                if (rlo == cb + 1)     e1 = 0.f;
                if (rlo + 8 == cb)     e2 = 0.f;
                if (rlo + 8 == cb + 1) e3 = 0.f;
            }
            slo += e0 + e1;
            shi += e2 + e3;
        }
        slo += __shfl_xor_sync(0xffffffffu, slo, 1);
        slo += __shfl_xor_sync(0xffffffffu, slo, 2);
        shi += __shfl_xor_sync(0xffffffffu, shi, 1);
        shi += __shfl_xor_sync(0xffffffffu, shi, 2);
        if ((l & 3) == 0) {
            rs[rlo][wc]     = slo;
            rs[rlo + 8][wc] = shi;
        }
    }
    __syncthreads();

    if (tid < 128) {
        float s = rs[tid][0] + rs[tid][1] + rs[tid][2] + rs[tid][3];
        g_partial[(size_t)(row0 + tid) * NCOLT + blockIdx.x] = s;
    }
}

// ---------------------------------------------------------------------------
// 3) reduce 32 column-tile partials per row -> neg_sumexp
// ---------------------------------------------------------------------------
__global__ void neg_reduce_kernel() {
    int r = blockIdx.x * 256 + threadIdx.x;
    float s = 0.f;
#pragma unroll
    for (int j = 0; j < NCOLT; j++) s += g_partial[(size_t)r * NCOLT + j];
    g_neg[r] = s;
}

// ---------------------------------------------------------------------------
// 4) pos similarities + per-pair loss; one warp per (b,p) pair (fp32 path).
// ---------------------------------------------------------------------------
__global__ void loss_kernel(const float* __restrict__ pos) {
    __shared__ float sh[8];
    int warp = threadIdx.x >> 5;
    int lane = threadIdx.x & 31;
    int pair = blockIdx.x * 8 + warp;
    int b    = pair >> 1;                  // P = 2

    const float4* pv = (const float4*)(pos + (size_t)pair * ND);
    const float4* av = (const float4*)(g_anorm + (size_t)b * ND);

    float dap = 0.f, dpp = 0.f;
#pragma unroll
    for (int q = 0; q < 4; q++) {
        float4 p4 = pv[lane + 32 * q];
        float4 a4 = av[lane + 32 * q];
        dap += a4.x * p4.x + a4.y * p4.y + a4.z * p4.z + a4.w * p4.w;
        dpp += p4.x * p4.x + p4.y * p4.y + p4.z * p4.z + p4.w * p4.w;
    }
#pragma unroll
    for (int o = 16; o > 0; o >>= 1) {
        dap += __shfl_xor_sync(0xffffffffu, dap, o);
        dpp += __shfl_xor_sync(0xffffffffu, dpp, o);
    }

    if (lane == 0) {
        float ps = dap * rsqrtf(dpp) * INV_T;
        float ep = expf(ps);
        sh[warp] = logf(ep + g_neg[b] + 1e-8f) - ps;
    }
    __syncthreads();
    if (threadIdx.x == 0) {
        float s = 0.f;
#pragma unroll
        for (int w = 0; w < 8; w++) s += sh[w];
        g_losspart[blockIdx.x] = s;
    }
}

// ---------------------------------------------------------------------------
// 5) final mean
// ---------------------------------------------------------------------------
__global__ void final_kernel(float* __restrict__ out) {
    __shared__ float sh[256];
    float s = 0.f;
    for (int i = threadIdx.x; i < 1024; i += 256) s += g_losspart[i];
    sh[threadIdx.x] = s;
    __syncthreads();
    for (int o = 128; o > 0; o >>= 1) {
        if (threadIdx.x < o) sh[threadIdx.x] += sh[threadIdx.x + o];
        __syncthreads();
    }
    if (threadIdx.x == 0) out[0] = sh[0] * (1.0f / (float)NPOS);
}

// ---------------------------------------------------------------------------
extern "C" void kernel_launch(void* const* d_in, const int* in_sizes, int n_in,
                              void* d_out, int out_size) {
    const float* anchor = (const float*)d_in[0];
    const float* pos    = (const float*)d_in[1];
    if (n_in >= 2 && in_sizes[0] > in_sizes[1]) {
        const float* t = anchor; anchor = pos; pos = t;
    }

    normalize_kernel<<<NB / 8, 256>>>(anchor);
    aa_mma_kernel<<<dim3(NCOLT, NCOLT), 256>>>();
    neg_reduce_kernel<<<NB / 256, 256>>>();
    loss_kernel<<<NPOS / 8, 256>>>(pos);
    final_kernel<<<1, 256>>>((float*)d_out);
}

// round 4
// speedup vs baseline: 8.6605x; 1.6031x over previous
#include <cuda_runtime.h>
#include <cuda_bf16.h>
#include <math.h>
#include <cstdint>

#define NB   4096
#define ND   512
#define NPOS 8192
#define INV_T 14.2857142857142857f
#define EXP2_SCALE 20.609929155566063f   /* INV_T * log2(e) */
#define NCOLT 32
#define NTILE (NCOLT * (NCOLT + 1) / 2)  /* 528 lower-triangular tiles */

// ---- scratch (no allocation allowed) ----
__device__ __nv_bfloat16 g_abf16[NB * ND];       // normalized anchors bf16
__device__ float         g_partial[NB * NCOLT];  // per-(row, coltile) exp-sums
__device__ float         g_losspart[1024];

__device__ __forceinline__ uint32_t smem_u32(const void* p) {
    uint32_t a;
    asm("{ .reg .u64 t; cvta.to.shared.u64 t, %1; cvt.u32.u64 %0, t; }" : "=r"(a) : "l"(p));
    return a;
}

// ---------------------------------------------------------------------------
// 1) L2-normalize anchors -> bf16. One warp per row.
// ---------------------------------------------------------------------------
__global__ void normalize_kernel(const float* __restrict__ a) {
    int warp = threadIdx.x >> 5;
    int lane = threadIdx.x & 31;
    int row  = blockIdx.x * 8 + warp;

    const float4* src = (const float4*)(a + (size_t)row * ND);
    uint2* bdst = (uint2*)(g_abf16 + (size_t)row * ND);

    float4 v[4];
    float ss = 0.f;
#pragma unroll
    for (int q = 0; q < 4; q++) {
        v[q] = src[lane + 32 * q];
        ss += v[q].x * v[q].x + v[q].y * v[q].y + v[q].z * v[q].z + v[q].w * v[q].w;
    }
#pragma unroll
    for (int o = 16; o > 0; o >>= 1) ss += __shfl_xor_sync(0xffffffffu, ss, o);

    float inv = rsqrtf(ss);
#pragma unroll
    for (int q = 0; q < 4; q++) {
        float4 w = v[q];
        w.x *= inv; w.y *= inv; w.z *= inv; w.w *= inv;
        __nv_bfloat162 lo = __floats2bfloat162_rn(w.x, w.y);
        __nv_bfloat162 hi = __floats2bfloat162_rn(w.z, w.w);
        uint2 pk;
        pk.x = *(uint32_t*)&lo;
        pk.y = *(uint32_t*)&hi;
        bdst[lane + 32 * q] = pk;
    }
}

// ---------------------------------------------------------------------------
// 2) mma.sync bf16 GEMM on the LOWER TRIANGLE of the 32x32 tile grid.
//    Tile (bx, by) with bx >= by: rows from block by, cols from block bx.
//    Row sums -> g_partial[row][bx]; col sums (off-diag) -> g_partial[col][by].
// ---------------------------------------------------------------------------
#define KC 32
#define NCHUNK (ND / KC)      // 16
#define TILE_BYTES (128 * 64) // 8KB

__global__ __launch_bounds__(256) void aa_mma_kernel() {
    __shared__ __align__(128) char sA[2][TILE_BYTES];
    __shared__ __align__(128) char sB[2][TILE_BYTES];
    __shared__ float rs_row[128][4];
    __shared__ float rs_col[128][2];

    // triangular decode: idx = bx*(bx+1)/2 + by, by <= bx
    const int idx = blockIdx.x;
    int bx = (int)((sqrtf(8.0f * idx + 1.0f) - 1.0f) * 0.5f);
    while ((bx + 1) * (bx + 2) / 2 <= idx) ++bx;
    while (bx * (bx + 1) / 2 > idx) --bx;
    const int by = idx - bx * (bx + 1) / 2;
    const bool diag = (bx == by);

    const int tid = threadIdx.x;
    const int wid = tid >> 5;
    const int l   = tid & 31;
    const int wr  = wid & 1;       // m offset 64*wr
    const int wc  = wid >> 1;      // n offset 32*wc
    const int row0 = by * 128;
    const int col0 = bx * 128;

    const uint32_t sa_base = smem_u32(sA);
    const uint32_t sb_base = smem_u32(sB);
    const char* gsrc = (const char*)g_abf16;

    const int ra = (l & 7) | (((l >> 3) & 1) << 3);
    const int sa_hi = l >> 4;
    const int rb = (l & 7) | ((l >> 4) << 3);
    const int sb_hi = (l >> 3) & 1;

    uint32_t offA[2], offB[2];
#pragma unroll
    for (int kc = 0; kc < 2; kc++) {
        offA[kc] = ra * 64 + (((2 * kc + sa_hi) ^ ((ra >> 1) & 3)) << 4);
        offB[kc] = rb * 64 + (((2 * kc + sb_hi) ^ ((rb >> 1) & 3)) << 4);
    }

    int ld_row[2], ld_slot[2];
    uint32_t ld_dst[2];
#pragma unroll
    for (int t = 0; t < 2; t++) {
        int i2 = tid + t * 256;
        ld_row[t]  = i2 >> 2;
        ld_slot[t] = i2 & 3;
        int sw = ld_slot[t] ^ ((ld_row[t] >> 1) & 3);
        ld_dst[t] = ld_row[t] * 64 + sw * 16;
    }

    float acc[4][4][4];
#pragma unroll
    for (int i = 0; i < 4; i++)
#pragma unroll
        for (int j = 0; j < 4; j++)
#pragma unroll
            for (int q = 0; q < 4; q++) acc[i][j][q] = 0.f;

#pragma unroll
    for (int t = 0; t < 2; t++) {
        const char* srcA = gsrc + ((size_t)(row0 + ld_row[t]) * ND + ld_slot[t] * 8) * 2;
        const char* srcB = gsrc + ((size_t)(col0 + ld_row[t]) * ND + ld_slot[t] * 8) * 2;
        asm volatile("cp.async.cg.shared.global [%0], [%1], 16;" :: "r"(sa_base + ld_dst[t]), "l"(srcA) : "memory");
        asm volatile("cp.async.cg.shared.global [%0], [%1], 16;" :: "r"(sb_base + ld_dst[t]), "l"(srcB) : "memory");
    }
    asm volatile("cp.async.commit_group;" ::: "memory");

    for (int c = 0; c < NCHUNK; c++) {
        int buf = c & 1;
        if (c + 1 < NCHUNK) {
            int nb = (c + 1) & 1;
            int kbyte = (c + 1) * KC * 2;
#pragma unroll
            for (int t = 0; t < 2; t++) {
                const char* srcA = gsrc + ((size_t)(row0 + ld_row[t]) * ND) * 2 + kbyte + ld_slot[t] * 16;
                const char* srcB = gsrc + ((size_t)(col0 + ld_row[t]) * ND) * 2 + kbyte + ld_slot[t] * 16;
                asm volatile("cp.async.cg.shared.global [%0], [%1], 16;" :: "r"(sa_base + nb * TILE_BYTES + ld_dst[t]), "l"(srcA) : "memory");
                asm volatile("cp.async.cg.shared.global [%0], [%1], 16;" :: "r"(sb_base + nb * TILE_BYTES + ld_dst[t]), "l"(srcB) : "memory");
            }
            asm volatile("cp.async.commit_group;" ::: "memory");
            asm volatile("cp.async.wait_group 1;" ::: "memory");
        } else {
            asm volatile("cp.async.wait_group 0;" ::: "memory");
        }
        __syncthreads();

        const uint32_t aw = sa_base + buf * TILE_BYTES + wr * 64 * 64;
        const uint32_t bw = sb_base + buf * TILE_BYTES + wc * 32 * 64;

#pragma unroll
        for (int kc = 0; kc < 2; kc++) {
            uint32_t af[4][4];
#pragma unroll
            for (int mf = 0; mf < 4; mf++) {
                asm volatile("ldmatrix.sync.aligned.m8n8.x4.shared.b16 {%0,%1,%2,%3}, [%4];"
                    : "=r"(af[mf][0]), "=r"(af[mf][1]), "=r"(af[mf][2]), "=r"(af[mf][3])
                    : "r"(aw + mf * 16 * 64 + offA[kc]));
            }
            uint32_t bf[4][2];
#pragma unroll
            for (int p = 0; p < 2; p++) {
                uint32_t r0, r1, r2, r3;
                asm volatile("ldmatrix.sync.aligned.m8n8.x4.shared.b16 {%0,%1,%2,%3}, [%4];"
                    : "=r"(r0), "=r"(r1), "=r"(r2), "=r"(r3)
                    : "r"(bw + p * 16 * 64 + offB[kc]));
                bf[2 * p][0] = r0; bf[2 * p][1] = r1;
                bf[2 * p + 1][0] = r2; bf[2 * p + 1][1] = r3;
            }
#pragma unroll
            for (int mf = 0; mf < 4; mf++)
#pragma unroll
                for (int nf = 0; nf < 4; nf++) {
                    asm volatile(
                        "mma.sync.aligned.m16n8k16.row.col.f32.bf16.bf16.f32 "
                        "{%0,%1,%2,%3}, {%4,%5,%6,%7}, {%8,%9}, {%0,%1,%2,%3};"
                        : "+f"(acc[mf][nf][0]), "+f"(acc[mf][nf][1]),
                          "+f"(acc[mf][nf][2]), "+f"(acc[mf][nf][3])
                        : "r"(af[mf][0]), "r"(af[mf][1]), "r"(af[mf][2]), "r"(af[mf][3]),
                          "r"(bf[nf][0]), "r"(bf[nf][1]));
                }
        }
        __syncthreads();
    }

    // ---- fused epilogue: exp, diag skip, row sums + (off-diag) col sums ----
    const int qrow = l >> 2;           // 0..7
    const int qcol = 2 * (l & 3);      // 0,2,4,6

    float cs0[4], cs1[4];
#pragma unroll
    for (int nf = 0; nf < 4; nf++) { cs0[nf] = 0.f; cs1[nf] = 0.f; }

#pragma unroll
    for (int mf = 0; mf < 4; mf++) {
        float slo = 0.f, shi = 0.f;
        int rlo = wr * 64 + mf * 16 + qrow;
#pragma unroll
        for (int nf = 0; nf < 4; nf++) {
            int cb = wc * 32 + nf * 8 + qcol;
            float e0 = exp2f(acc[mf][nf][0] * EXP2_SCALE);
            float e1 = exp2f(acc[mf][nf][1] * EXP2_SCALE);
            float e2 = exp2f(acc[mf][nf][2] * EXP2_SCALE);
            float e3 = exp2f(acc[mf][nf][3] * EXP2_SCALE);
            if (diag) {
                if (rlo == cb)         e0 = 0.f;
                if (rlo == cb + 1)     e1 = 0.f;
                if (rlo + 8 == cb)     e2 = 0.f;
                if (rlo + 8 == cb + 1) e3 = 0.f;
            }
            slo += e0 + e1;
            shi += e2 + e3;
            cs0[nf] += e0 + e2;
            cs1[nf] += e1 + e3;
        }
        slo += __shfl_xor_sync(0xffffffffu, slo, 1);
        slo += __shfl_xor_sync(0xffffffffu, slo, 2);
        shi += __shfl_xor_sync(0xffffffffu, shi, 1);
        shi += __shfl_xor_sync(0xffffffffu, shi, 2);
        if ((l & 3) == 0) {
            rs_row[rlo][wc]     = slo;
            rs_row[rlo + 8][wc] = shi;
        }
    }

    if (!diag) {
#pragma unroll
        for (int nf = 0; nf < 4; nf++) {
#pragma unroll
            for (int o = 4; o <= 16; o <<= 1) {
                cs0[nf] += __shfl_xor_sync(0xffffffffu, cs0[nf], o);
                cs1[nf] += __shfl_xor_sync(0xffffffffu, cs1[nf], o);
            }
            if (l < 4) {
                int cb = wc * 32 + nf * 8 + qcol;   // qcol = 2*l here
                rs_col[cb][wr]     = cs0[nf];
                rs_col[cb + 1][wr] = cs1[nf];
            }
        }
    }
    __syncthreads();

    if (tid < 128) {
        float s = rs_row[tid][0] + rs_row[tid][1] + rs_row[tid][2] + rs_row[tid][3];
        g_partial[(size_t)(row0 + tid) * NCOLT + bx] = s;
        if (!diag) {
            float csum = rs_col[tid][0] + rs_col[tid][1];
            g_partial[(size_t)(col0 + tid) * NCOLT + by] = csum;
        }
    }
}

// ---------------------------------------------------------------------------
// 3) loss: one warp per (b,p) pair; fuses neg_sumexp reduction (32 partials
//    per row) and on-the-fly anchor renormalization from raw input.
// ---------------------------------------------------------------------------
__global__ __launch_bounds__(256) void loss_kernel(const float* __restrict__ anchor,
                                                   const float* __restrict__ pos) {
    __shared__ float sh[8];
    int warp = threadIdx.x >> 5;
    int lane = threadIdx.x & 31;
    int pair = blockIdx.x * 8 + warp;
    int b    = pair >> 1;                  // P = 2

    const float4* pv = (const float4*)(pos + (size_t)pair * ND);
    const float4* av = (const float4*)(anchor + (size_t)b * ND);

    // fire all loads first for max MLP
    float np = g_partial[(size_t)b * NCOLT + lane];
    float4 p4[4], a4[4];
#pragma unroll
    for (int q = 0; q < 4; q++) p4[q] = pv[lane + 32 * q];
#pragma unroll
    for (int q = 0; q < 4; q++) a4[q] = av[lane + 32 * q];

    float dap = 0.f, dpp = 0.f, daa = 0.f;
#pragma unroll
    for (int q = 0; q < 4; q++) {
        dap += a4[q].x * p4[q].x + a4[q].y * p4[q].y + a4[q].z * p4[q].z + a4[q].w * p4[q].w;
        dpp += p4[q].x * p4[q].x + p4[q].y * p4[q].y + p4[q].z * p4[q].z + p4[q].w * p4[q].w;
        daa += a4[q].x * a4[q].x + a4[q].y * a4[q].y + a4[q].z * a4[q].z + a4[q].w * a4[q].w;
    }
#pragma unroll
    for (int o = 16; o > 0; o >>= 1) {
        dap += __shfl_xor_sync(0xffffffffu, dap, o);
        dpp += __shfl_xor_sync(0xffffffffu, dpp, o);
        daa += __shfl_xor_sync(0xffffffffu, daa, o);
        np  += __shfl_xor_sync(0xffffffffu, np, o);
    }

    if (lane == 0) {
        float ps = dap * rsqrtf(dpp * daa) * INV_T;
        float ep = expf(ps);
        sh[warp] = logf(ep + np + 1e-8f) - ps;
    }
    __syncthreads();
    if (threadIdx.x == 0) {
        float s = 0.f;
#pragma unroll
        for (int w = 0; w < 8; w++) s += sh[w];
        g_losspart[blockIdx.x] = s;
    }
}

// ---------------------------------------------------------------------------
// 4) final mean
// ---------------------------------------------------------------------------
__global__ void final_kernel(float* __restrict__ out) {
    __shared__ float sh[256];
    float s = 0.f;
    for (int i = threadIdx.x; i < 1024; i += 256) s += g_losspart[i];
    sh[threadIdx.x] = s;
    __syncthreads();
    for (int o = 128; o > 0; o >>= 1) {
        if (threadIdx.x < o) sh[threadIdx.x] += sh[threadIdx.x + o];
        __syncthreads();
    }
    if (threadIdx.x == 0) out[0] = sh[0] * (1.0f / (float)NPOS);
}

// ---------------------------------------------------------------------------
extern "C" void kernel_launch(void* const* d_in, const int* in_sizes, int n_in,
                              void* d_out, int out_size) {
    const float* anchor = (const float*)d_in[0];
    const float* pos    = (const float*)d_in[1];
    if (n_in >= 2 && in_sizes[0] > in_sizes[1]) {
        const float* t = anchor; anchor = pos; pos = t;
    }

    normalize_kernel<<<NB / 8, 256>>>(anchor);
    aa_mma_kernel<<<NTILE, 256>>>();
    loss_kernel<<<NPOS / 8, 256>>>(anchor, pos);
    final_kernel<<<1, 256>>>((float*)d_out);
}